// round 7
// baseline (speedup 1.0000x reference)
#include <cuda_runtime.h>
#include <cstdint>

#define EMB 64
#define NN_MAX 50000
#define NSCAN 50176          // 49 * 1024
#define NE_MAX 800000
#define NE_PAD (NE_MAX + 64)

// ---------------- scratch (static device memory; no allocations) ----------------
__device__ __align__(128) float g_h  [NN_MAX * EMB];
__device__ __align__(128) float g_Pab[NN_MAX * 128];   // [Pa | Pb] per node
__device__ __align__(128) float g_agg[NN_MAX * EMB];   // zero at launch entry (invariant)
__device__ int g_is64;

// sort scratch
__device__ int   g_cnt [NSCAN];
__device__ int   g_inc [NSCAN];
__device__ int   g_cur [NSCAN];
__device__ int   g_bsum[64];
__device__ __align__(128) int   g_srcS[NE_PAD];
__device__ __align__(128) int   g_dstS[NE_PAD];
__device__ __align__(128) float g_eaS [NE_PAD * 6];

// ---------------- helpers ------------------------------------------------------
__device__ __forceinline__ uint32_t f32_to_tf32(float f) {
    uint32_t u;
    asm("cvt.rna.tf32.f32 %0, %1;" : "=r"(u) : "f"(f));
    return u;
}
__device__ __forceinline__ void split_tf32(float v, uint32_t& hi, uint32_t& lo) {
    hi = f32_to_tf32(v);
    lo = f32_to_tf32(v - __uint_as_float(hi));
}
__device__ __forceinline__ void mma_tf32(float* c, const uint32_t* a, const uint32_t* b) {
    asm volatile(
        "mma.sync.aligned.m16n8k8.row.col.f32.tf32.tf32.f32 "
        "{%0,%1,%2,%3}, {%4,%5,%6,%7}, {%8,%9}, {%0,%1,%2,%3};"
        : "+f"(c[0]), "+f"(c[1]), "+f"(c[2]), "+f"(c[3])
        : "r"(a[0]), "r"(a[1]), "r"(a[2]), "r"(a[3]), "r"(b[0]), "r"(b[1]));
}

// 3xTF32 warp GEMM: acc[NTILES][4] += A(16 x 8*KSTEPS) * W, ~fp32 precision
template<int KSTEPS, int NTILES, int AST, int WST>
__device__ __forceinline__ void mma_steps3(const uint32_t* aH, const uint32_t* aL,
                                           const uint32_t* wH, const uint32_t* wL,
                                           float (*acc)[4], int lg, int lt)
{
#pragma unroll
    for (int s = 0; s < KSTEPS; s++) {
        const int k0 = 8 * s;
        uint32_t afH[4], afL[4];
        const uint32_t* abH = aH + lg * AST + k0 + lt;
        const uint32_t* abL = aL + lg * AST + k0 + lt;
        afH[0] = abH[0]; afH[1] = abH[8 * AST]; afH[2] = abH[4]; afH[3] = abH[8 * AST + 4];
        afL[0] = abL[0]; afL[1] = abL[8 * AST]; afL[2] = abL[4]; afL[3] = abL[8 * AST + 4];
#pragma unroll
        for (int j = 0; j < NTILES; j++) {
            uint32_t bfH[2], bfL[2];
            bfH[0] = wH[(k0 + lt)     * WST + 8 * j + lg];
            bfH[1] = wH[(k0 + lt + 4) * WST + 8 * j + lg];
            bfL[0] = wL[(k0 + lt)     * WST + 8 * j + lg];
            bfL[1] = wL[(k0 + lt + 4) * WST + 8 * j + lg];
            mma_tf32(acc[j], afH, bfL);
            mma_tf32(acc[j], afL, bfH);
            mma_tf32(acc[j], afH, bfH);
        }
    }
}

// stage 16 rows x 32 k-cols of A into warp hi/lo tiles (stride 36)
template<bool ZERO_AFTER>
__device__ __forceinline__ void stage_chunk3(uint32_t* aH, uint32_t* aL,
                                             const float* A, float* Az,
                                             int rowK, long long row0, int kc, int M, int l)
{
#pragma unroll
    for (int q = 0; q < 4; q++) {
        const int i = l + 32 * q;
        const int r = i >> 3;
        const int c4 = (i & 7) * 4;
        const long long grow = row0 + r;
        float4 v = make_float4(0.f, 0.f, 0.f, 0.f);
        if (grow < M) {
            v = *(const float4*)(A + grow * rowK + kc + c4);
            if (ZERO_AFTER)
                *(float4*)(Az + grow * rowK + kc + c4) = make_float4(0.f, 0.f, 0.f, 0.f);
        }
        uint4 th, tl;
        split_tf32(v.x, th.x, tl.x); split_tf32(v.y, th.y, tl.y);
        split_tf32(v.z, th.z, tl.z); split_tf32(v.w, th.w, tl.w);
        *(uint4*)(aH + r * 36 + c4) = th;
        *(uint4*)(aL + r * 36 + c4) = tl;
    }
}

// ---------------- detect whether edge_index is int64 or int32 ----------------
__global__ void detect_idx_kernel(const unsigned int* __restrict__ p)
{
    if (threadIdx.x == 0 && blockIdx.x == 0) {
        unsigned int v = 0;
#pragma unroll
        for (int k = 0; k < 64; k++) v |= p[2 * k + 1];
        g_is64 = (v == 0) ? 1 : 0;
    }
}

// ---------------- counting sort by dst ----------------------------------------
__global__ void hist_kernel(const void* __restrict__ ei, int E)
{
    const int is64 = g_is64;
    for (long long e = (long long)blockIdx.x * blockDim.x + threadIdx.x; e < E;
         e += (long long)gridDim.x * blockDim.x) {
        int dst = is64 ? (int)((const long long*)ei)[(long long)E + e]
                       : ((const int*)ei)[(long long)E + e];
        atomicAdd(&g_cnt[dst], 1);
    }
}

__global__ __launch_bounds__(1024) void scan1_kernel()
{
    const int t = threadIdx.x, b = blockIdx.x;
    const int i = b * 1024 + t;
    const int lane = t & 31, wid = t >> 5;
    int x = g_cnt[i];
#pragma unroll
    for (int s = 1; s < 32; s <<= 1) {
        int u = __shfl_up_sync(0xffffffffu, x, s);
        if (lane >= s) x += u;
    }
    __shared__ int ws[32];
    if (lane == 31) ws[wid] = x;
    __syncthreads();
    if (wid == 0) {
        int y = ws[lane];
#pragma unroll
        for (int s = 1; s < 32; s <<= 1) {
            int u = __shfl_up_sync(0xffffffffu, y, s);
            if (lane >= s) y += u;
        }
        ws[lane] = y;
    }
    __syncthreads();
    int inc = x + (wid ? ws[wid - 1] : 0);
    g_inc[i] = inc;
    if (t == 1023) g_bsum[b] = inc;
}

__global__ void scan2_kernel(int nb)
{
    if (threadIdx.x == 0 && blockIdx.x == 0) {
        int run = 0;
        for (int b = 0; b < nb; b++) { int t = g_bsum[b]; g_bsum[b] = run; run += t; }
    }
}

__global__ __launch_bounds__(1024) void scan3_kernel()
{
    const int i = blockIdx.x * 1024 + threadIdx.x;
    g_cur[i] = g_inc[i] - g_cnt[i] + g_bsum[blockIdx.x];
}

__global__ void scatter_kernel(const void* __restrict__ ei,
                               const float* __restrict__ eattr, int E)
{
    const int is64 = g_is64;
    for (long long e = (long long)blockIdx.x * blockDim.x + threadIdx.x; e < E;
         e += (long long)gridDim.x * blockDim.x) {
        int src, dst;
        if (is64) {
            src = (int)((const long long*)ei)[e];
            dst = (int)((const long long*)ei)[(long long)E + e];
        } else {
            src = ((const int*)ei)[e];
            dst = ((const int*)ei)[(long long)E + e];
        }
        int pos = atomicAdd(&g_cur[dst], 1);
        g_srcS[pos] = src;
        g_dstS[pos] = dst;
#pragma unroll
        for (int q = 0; q < 6; q++) g_eaS[(long long)pos * 6 + q] = eattr[e * 6 + q];
    }
}

// ---------------- proj: h = x(Mx128) @ W(128x64) + b  (3xTF32) -----------------
__global__ __launch_bounds__(256)
void proj_tf32(const float* __restrict__ x, const float* __restrict__ W,
               const float* __restrict__ b, float* __restrict__ C, int M)
{
    extern __shared__ __align__(16) char smem[];
    uint32_t* sWh = (uint32_t*)smem;                 // 128 x 72
    uint32_t* sWl = (uint32_t*)(smem + 36864);       // 128 x 72
    float*    sB  = (float*)(smem + 73728);          // 64
    uint32_t* sAh = (uint32_t*)(smem + 73984);       // 8 x 16 x 36
    uint32_t* sAl = (uint32_t*)(smem + 92416);       // 8 x 16 x 36

    const int tid = threadIdx.x, w = tid >> 5, l = tid & 31;
    const int lg = l >> 2, lt = l & 3;

    for (int i = tid; i < 128 * 64; i += 256) {
        int k = i >> 6, n = i & 63;
        uint32_t hi, lo;
        split_tf32(W[i], hi, lo);
        sWh[k * 72 + n] = hi;
        sWl[k * 72 + n] = lo;
    }
    if (tid < 64) sB[tid] = b[tid];
    __syncthreads();

    uint32_t* aH = sAh + w * (16 * 36);
    uint32_t* aL = sAl + w * (16 * 36);
    const long long row0 = (long long)blockIdx.x * 128 + w * 16;

    float acc[8][4];
#pragma unroll
    for (int j = 0; j < 8; j++) {
        acc[j][0] = acc[j][2] = sB[8 * j + 2 * lt];
        acc[j][1] = acc[j][3] = sB[8 * j + 2 * lt + 1];
    }

#pragma unroll
    for (int kc = 0; kc < 128; kc += 32) {
        stage_chunk3<false>(aH, aL, x, nullptr, 128, row0, kc, M, l);
        __syncwarp();
        mma_steps3<4, 8, 36, 72>(aH, aL, sWh + kc * 72, sWl + kc * 72, acc, lg, lt);
        __syncwarp();
    }

#pragma unroll
    for (int j = 0; j < 8; j++) {
        const int col = 8 * j + 2 * lt;
        long long ra = row0 + lg, rb = row0 + lg + 8;
        if (ra < M) *(float2*)(C + ra * 64 + col) = make_float2(acc[j][0], acc[j][1]);
        if (rb < M) *(float2*)(C + rb * 64 + col) = make_float2(acc[j][2], acc[j][3]);
    }
}

// ---------------- dual: Pab = [h@W1a + b1 | h@W1b]  (3xTF32) -------------------
__global__ __launch_bounds__(256)
void dual_tf32(const float* __restrict__ h, const float* __restrict__ W1,
               const float* __restrict__ b1, float* __restrict__ Pab, int M)
{
    extern __shared__ __align__(16) char smem[];
    uint32_t* sWh = (uint32_t*)smem;                 // 64 x 136
    uint32_t* sWl = (uint32_t*)(smem + 34816);       // 64 x 136
    float*    sB  = (float*)(smem + 69632);          // 64
    uint32_t* sAh = (uint32_t*)(smem + 69888);       // 8 x 16 x 36
    uint32_t* sAl = (uint32_t*)(smem + 88320);       // 8 x 16 x 36

    const int tid = threadIdx.x, w = tid >> 5, l = tid & 31;
    const int lg = l >> 2, lt = l & 3;

    for (int i = tid; i < 64 * 128; i += 256) {
        int k = i >> 7, n = i & 127;
        float v = (n < 64) ? W1[k * 64 + n] : W1[(64 + k) * 64 + (n - 64)];
        uint32_t hi, lo;
        split_tf32(v, hi, lo);
        sWh[k * 136 + n] = hi;
        sWl[k * 136 + n] = lo;
    }
    if (tid < 64) sB[tid] = b1[tid];
    __syncthreads();

    uint32_t* aH = sAh + w * (16 * 36);
    uint32_t* aL = sAl + w * (16 * 36);
    const long long row0 = (long long)blockIdx.x * 128 + w * 16;

    float acc[16][4];
#pragma unroll
    for (int j = 0; j < 16; j++) {
        const int col = 8 * j + 2 * lt;
        float b0 = (col < 64) ? sB[col] : 0.0f;
        float b1v = (col < 64) ? sB[col + 1] : 0.0f;
        acc[j][0] = acc[j][2] = b0;
        acc[j][1] = acc[j][3] = b1v;
    }

#pragma unroll
    for (int kc = 0; kc < 64; kc += 32) {
        stage_chunk3<false>(aH, aL, h, nullptr, 64, row0, kc, M, l);
        __syncwarp();
        mma_steps3<4, 16, 36, 136>(aH, aL, sWh + kc * 136, sWl + kc * 136, acc, lg, lt);
        __syncwarp();
    }

#pragma unroll
    for (int j = 0; j < 16; j++) {
        const int col = 8 * j + 2 * lt;
        long long ra = row0 + lg, rb = row0 + lg + 8;
        if (ra < M) *(float2*)(Pab + ra * 128 + col) = make_float2(acc[j][0], acc[j][1]);
        if (rb < M) *(float2*)(Pab + rb * 128 + col) = make_float2(acc[j][2], acc[j][3]);
    }
}

// ---------------- fused update: h += relu(relu([h|agg]@U1+b1)@U2+b2) (3xTF32) --
// Zeroes agg after reading (restores launch-entry invariant).
__global__ __launch_bounds__(256)
void update_tf32(const float* __restrict__ h_in, const float* __restrict__ U1,
                 const float* __restrict__ b1, const float* __restrict__ U2,
                 const float* __restrict__ b2, float* agg,
                 float* __restrict__ h_out, int M)
{
    extern __shared__ __align__(16) char smem[];
    uint32_t* sW1h = (uint32_t*)smem;                  // 128 x 72
    uint32_t* sW1l = (uint32_t*)(smem + 36864);        // 128 x 72
    uint32_t* sU2h = (uint32_t*)(smem + 73728);        // 64 x 72
    uint32_t* sU2l = (uint32_t*)(smem + 92160);        // 64 x 72
    float*    sB1  = (float*)(smem + 110592);          // 64
    float*    sB2  = (float*)(smem + 110848);          // 64
    uint32_t* sAh  = (uint32_t*)(smem + 111104);       // 8 x 16 x 36
    uint32_t* sAl  = (uint32_t*)(smem + 129536);       // 8 x 16 x 36
    uint32_t* sU1h = (uint32_t*)(smem + 147968);       // 8 x 16 x 68
    uint32_t* sU1l = (uint32_t*)(smem + 182784);       // 8 x 16 x 68

    const int tid = threadIdx.x, w = tid >> 5, l = tid & 31;
    const int lg = l >> 2, lt = l & 3;

    for (int i = tid; i < 128 * 64; i += 256) {
        int k = i >> 6, n = i & 63;
        uint32_t hi, lo;
        split_tf32(U1[i], hi, lo);
        sW1h[k * 72 + n] = hi;
        sW1l[k * 72 + n] = lo;
    }
    for (int i = tid; i < 64 * 64; i += 256) {
        int k = i >> 6, n = i & 63;
        uint32_t hi, lo;
        split_tf32(U2[i], hi, lo);
        sU2h[k * 72 + n] = hi;
        sU2l[k * 72 + n] = lo;
    }
    if (tid < 64) { sB1[tid] = b1[tid]; sB2[tid] = b2[tid]; }
    __syncthreads();

    uint32_t* aH  = sAh  + w * (16 * 36);
    uint32_t* aL  = sAl  + w * (16 * 36);
    uint32_t* u1H = sU1h + w * (16 * 68);
    uint32_t* u1L = sU1l + w * (16 * 68);
    const long long row0 = (long long)blockIdx.x * 128 + w * 16;

    // phase 1: u1 = relu([h|agg] @ U1 + b1)
    float acc[8][4];
#pragma unroll
    for (int j = 0; j < 8; j++) {
        acc[j][0] = acc[j][2] = sB1[8 * j + 2 * lt];
        acc[j][1] = acc[j][3] = sB1[8 * j + 2 * lt + 1];
    }

#pragma unroll
    for (int p = 0; p < 2; p++) {
        const float* A = p ? agg : h_in;
#pragma unroll
        for (int kc = 0; kc < 64; kc += 32) {
            if (p == 0) stage_chunk3<false>(aH, aL, A, nullptr, 64, row0, kc, M, l);
            else        stage_chunk3<true >(aH, aL, A, agg,     64, row0, kc, M, l);
            __syncwarp();
            mma_steps3<4, 8, 36, 72>(aH, aL, sW1h + (p * 64 + kc) * 72,
                                     sW1l + (p * 64 + kc) * 72, acc, lg, lt);
            __syncwarp();
        }
    }

    // write u1 (relu) hi/lo to warp-private tiles, stride 68
#pragma unroll
    for (int j = 0; j < 8; j++) {
        const int col = 8 * j + 2 * lt;
        uint32_t h0, l0, h1, l1, h2, l2, h3, l3;
        split_tf32(fmaxf(acc[j][0], 0.f), h0, l0);
        split_tf32(fmaxf(acc[j][1], 0.f), h1, l1);
        split_tf32(fmaxf(acc[j][2], 0.f), h2, l2);
        split_tf32(fmaxf(acc[j][3], 0.f), h3, l3);
        *(uint2*)(u1H + lg * 68 + col)       = make_uint2(h0, h1);
        *(uint2*)(u1H + (lg + 8) * 68 + col) = make_uint2(h2, h3);
        *(uint2*)(u1L + lg * 68 + col)       = make_uint2(l0, l1);
        *(uint2*)(u1L + (lg + 8) * 68 + col) = make_uint2(l2, l3);
    }
    __syncwarp();

    // phase 2: h += relu(u1 @ U2 + b2)
    float acc2[8][4];
#pragma unroll
    for (int j = 0; j < 8; j++) {
        acc2[j][0] = acc2[j][2] = sB2[8 * j + 2 * lt];
        acc2[j][1] = acc2[j][3] = sB2[8 * j + 2 * lt + 1];
    }
    mma_steps3<8, 8, 68, 72>(u1H, u1L, sU2h, sU2l, acc2, lg, lt);

#pragma unroll
    for (int j = 0; j < 8; j++) {
        const int col = 8 * j + 2 * lt;
        long long ra = row0 + lg, rb = row0 + lg + 8;
        if (ra < M) {
            float2 hh = *(float2*)(h_out + ra * 64 + col);
            hh.x += fmaxf(acc2[j][0], 0.f);
            hh.y += fmaxf(acc2[j][1], 0.f);
            *(float2*)(h_out + ra * 64 + col) = hh;
        }
        if (rb < M) {
            float2 hh = *(float2*)(h_out + rb * 64 + col);
            hh.x += fmaxf(acc2[j][2], 0.f);
            hh.y += fmaxf(acc2[j][3], 0.f);
            *(float2*)(h_out + rb * 64 + col) = hh;
        }
    }
}

// ---------------- edge kernel: sorted edges, tf32 mma, segmented-scan scatter --
#define A_STRIDE 68
#define W_STRIDE 72
__global__ __launch_bounds__(256, 2)
void edge_kernel_mma(const float* __restrict__ Pab,
                     const float* __restrict__ W1c,   // 6 x 64
                     const float* __restrict__ W2,    // 64 x 64 (k x n)
                     const float* __restrict__ b2,    // 64
                     float* __restrict__ agg, int E)
{
    extern __shared__ __align__(16) char smem[];
    uint32_t* sA   = (uint32_t*)smem;                       // 8 warps x 32 x 68
    uint32_t* sW2  = (uint32_t*)(smem + 69632);             // 64 x 72 (tf32)
    float*    sW1c = (float*)(smem + 88064);                // 6 x 64
    float*    sB2  = (float*)(smem + 89600);                // 64
    float*    sEa  = (float*)(smem + 89856);                // 8 warps x 192

    const int tid = threadIdx.x;
    const int w   = tid >> 5;
    const int l   = tid & 31;

    for (int i = tid; i < 64 * 64; i += 256) {
        int k = i >> 6, n = i & 63;
        sW2[k * W_STRIDE + n] = f32_to_tf32(W2[i]);
    }
    for (int i = tid; i < 384; i += 256) sW1c[i] = W1c[i];
    if (tid < 64) sB2[tid] = b2[tid];
    __syncthreads();

    uint32_t* myA  = sA + w * 32 * A_STRIDE;
    float*    myF  = (float*)myA;
    float*    myEa = sEa + w * 192;
    const int gw = blockIdx.x * 8 + w;
    const int nW = gridDim.x * 8;
    const int nChunks = (E + 31) >> 5;

    const int lg = l >> 2;
    const int lt = l & 3;
    const int er = l >> 3;
    const int c4 = (l & 7) * 4;

    unsigned lm_le;
    asm("mov.u32 %0, %%lanemask_le;" : "=r"(lm_le));

    for (int ch = gw; ch < nChunks; ch += nW) {
        const long long e0 = (long long)ch << 5;
        const long long eg = e0 + l;
        const bool valid = eg < E;

        int src = 0, dst = -1;
        if (valid) {
            src = g_srcS[eg];
            dst = g_dstS[eg];
        }
        {
            const float4* gsrc = (const float4*)(g_eaS + e0 * 6);
            if (l < 16) {
                *(float4*)(myEa + 4 * l)        = gsrc[l];
                *(float4*)(myEa + 4 * (l + 16)) = gsrc[l + 16];
                *(float4*)(myEa + 4 * (l + 32)) = gsrc[l + 32];
            }
        }
        __syncwarp();

#pragma unroll
        for (int it = 0; it < 8; it++) {
            const int e = 4 * it + er;
            const int de = __shfl_sync(0xffffffffu, dst, e);
            const int se = __shfl_sync(0xffffffffu, src, e);
            const bool ev = (e0 + e) < E;
            const float* par = Pab + (long long)de * 128;
            const float* pbr = Pab + (long long)se * 128 + 64;
#pragma unroll
            for (int h = 0; h < 2; h++) {
                const int c = c4 + 32 * h;
                float v0 = 0.f, v1 = 0.f, v2 = 0.f, v3 = 0.f;
                if (ev) {
                    float4 a = *(const float4*)(par + c);
                    float4 b = *(const float4*)(pbr + c);
                    v0 = a.x + b.x; v1 = a.y + b.y; v2 = a.z + b.z; v3 = a.w + b.w;
#pragma unroll
                    for (int q = 0; q < 6; q++) {
                        float  eq = myEa[e * 6 + q];
                        float4 wv = *(const float4*)(sW1c + q * 64 + c);
                        v0 = fmaf(eq, wv.x, v0);
                        v1 = fmaf(eq, wv.y, v1);
                        v2 = fmaf(eq, wv.z, v2);
                        v3 = fmaf(eq, wv.w, v3);
                    }
                }
                uint32_t r0 = f32_to_tf32(fmaxf(v0, 0.f));
                uint32_t r1 = f32_to_tf32(fmaxf(v1, 0.f));
                uint32_t r2 = f32_to_tf32(fmaxf(v2, 0.f));
                uint32_t r3 = f32_to_tf32(fmaxf(v3, 0.f));
                *(uint4*)(myA + e * A_STRIDE + c) = make_uint4(r0, r1, r2, r3);
            }
        }
        __syncwarp();

        float acc[2][8][4];
#pragma unroll
        for (int g = 0; g < 2; g++)
#pragma unroll
            for (int j = 0; j < 8; j++)
#pragma unroll
                for (int q = 0; q < 4; q++) acc[g][j][q] = 0.0f;

#pragma unroll
        for (int s = 0; s < 8; s++) {
            const int k0 = 8 * s;
            uint32_t bf[8][2];
#pragma unroll
            for (int j = 0; j < 8; j++) {
                bf[j][0] = sW2[(k0 + lt)     * W_STRIDE + 8 * j + lg];
                bf[j][1] = sW2[(k0 + lt + 4) * W_STRIDE + 8 * j + lg];
            }
            uint32_t af[2][4];
#pragma unroll
            for (int g = 0; g < 2; g++) {
                const uint32_t* base = myA + (16 * g + lg) * A_STRIDE + k0 + lt;
                af[g][0] = base[0];
                af[g][1] = base[8 * A_STRIDE];
                af[g][2] = base[4];
                af[g][3] = base[8 * A_STRIDE + 4];
            }
#pragma unroll
            for (int g = 0; g < 2; g++)
#pragma unroll
                for (int j = 0; j < 8; j++)
                    mma_tf32(acc[g][j], af[g], bf[j]);
        }
        __syncwarp();

#pragma unroll
        for (int g = 0; g < 2; g++)
#pragma unroll
            for (int h = 0; h < 2; h++) {
                const int row = 16 * g + 8 * h + lg;
#pragma unroll
                for (int j = 0; j < 8; j++)
                    *(float2*)(myF + row * A_STRIDE + 8 * j + 2 * lt) =
                        make_float2(acc[g][j][2 * h], acc[g][j][2 * h + 1]);
            }
        __syncwarp();

        {
            const int dprev = __shfl_up_sync(0xffffffffu, dst, 1);
            const int dnext = __shfl_down_sync(0xffffffffu, dst, 1);
            const bool head = (l == 0) || (dprev != dst);
            const bool tail = (l == 31) || (dnext != dst);
            const unsigned hm = __ballot_sync(0xffffffffu, head);
            const int hs = 31 - __clz(hm & lm_le);
            const int dist = l - hs;
            float* p = agg + (long long)dst * 64;
#pragma unroll
            for (int u = 0; u < 16; u++) {
                float4 t  = *(const float4*)(myF + l * A_STRIDE + 4 * u);
                float4 bb = *(const float4*)(sB2 + 4 * u);
                float x0 = 0.f, x1 = 0.f, x2 = 0.f, x3 = 0.f;
                if (valid) {
                    x0 = fmaxf(t.x + bb.x, 0.f);
                    x1 = fmaxf(t.y + bb.y, 0.f);
                    x2 = fmaxf(t.z + bb.z, 0.f);
                    x3 = fmaxf(t.w + bb.w, 0.f);
                }
#pragma unroll
                for (int s = 1; s < 32; s <<= 1) {
                    float y0 = __shfl_up_sync(0xffffffffu, x0, s);
                    float y1 = __shfl_up_sync(0xffffffffu, x1, s);
                    float y2 = __shfl_up_sync(0xffffffffu, x2, s);
                    float y3 = __shfl_up_sync(0xffffffffu, x3, s);
                    if (dist >= s) { x0 += y0; x1 += y1; x2 += y2; x3 += y3; }
                }
                if (tail && valid)
                    asm volatile("red.global.add.v4.f32 [%0], {%1, %2, %3, %4};"
                                 :: "l"(p + 4 * u), "f"(x0), "f"(x1), "f"(x2), "f"(x3)
                                 : "memory");
            }
        }
        __syncwarp();
    }
}

// ---------------- prediction head ---------------------------------------------
__global__ __launch_bounds__(256)
void pred_kernel(const float* __restrict__ h, const float* __restrict__ pw,
                 const float* __restrict__ pb, float* __restrict__ out, int M)
{
    __shared__ float spw[64];
    __shared__ float swarp[8];
    if (threadIdx.x < 64) spw[threadIdx.x] = pw[threadIdx.x];
    __syncthreads();

    float sum = 0.0f;
    for (long long row = (long long)blockIdx.x * blockDim.x + threadIdx.x; row < M;
         row += (long long)gridDim.x * blockDim.x) {
        const float4* hr = (const float4*)(h + row * 64);
#pragma unroll
        for (int u = 0; u < 16; u++) {
            float4 v = hr[u];
            sum = fmaf(v.x, spw[4 * u + 0], sum);
            sum = fmaf(v.y, spw[4 * u + 1], sum);
            sum = fmaf(v.z, spw[4 * u + 2], sum);
            sum = fmaf(v.w, spw[4 * u + 3], sum);
        }
    }
#pragma unroll
    for (int o = 16; o > 0; o >>= 1) sum += __shfl_down_sync(0xffffffffu, sum, o);
    if ((threadIdx.x & 31) == 0) swarp[threadIdx.x >> 5] = sum;
    __syncthreads();
    if (threadIdx.x < 8) {
        float s = swarp[threadIdx.x];
#pragma unroll
        for (int o = 4; o > 0; o >>= 1) s += __shfl_down_sync(0xffu, s, o);
        if (threadIdx.x == 0) {
            if (blockIdx.x == 0) s = fmaf(pb[0], (float)M, s);
            atomicAdd(out, s);
        }
    }
}

// ---------------- launch ------------------------------------------------------
extern "C" void kernel_launch(void* const* d_in, const int* in_sizes, int n_in,
                              void* d_out, int out_size)
{
    const float* x       = (const float*)d_in[0];
    const void*  ei      = d_in[1];
    const float* eattr   = (const float*)d_in[2];
    const float* lin_w   = (const float*)d_in[3];
    const float* lin_b   = (const float*)d_in[4];
    const float* msg_w1  = (const float*)d_in[5];
    const float* msg_b1  = (const float*)d_in[6];
    const float* msg_w2  = (const float*)d_in[7];
    const float* msg_b2  = (const float*)d_in[8];
    const float* upd_w1  = (const float*)d_in[9];
    const float* upd_b1  = (const float*)d_in[10];
    const float* upd_w2  = (const float*)d_in[11];
    const float* upd_b2  = (const float*)d_in[12];
    const float* pred_w  = (const float*)d_in[13];
    const float* pred_b  = (const float*)d_in[14];

    const int M = in_sizes[0] / 128;   // 50000
    const int E = in_sizes[2] / 6;     // 800000

    float *h, *Pab, *agg;
    int* cnt;
    cudaGetSymbolAddress((void**)&h,   g_h);
    cudaGetSymbolAddress((void**)&Pab, g_Pab);
    cudaGetSymbolAddress((void**)&agg, g_agg);
    cudaGetSymbolAddress((void**)&cnt, g_cnt);

    const int gN = (M + 127) / 128;
    const int SM_EDGE = 96000, SM_PROJ = 110848, SM_DUAL = 106752, SM_UPD = 217600;
    cudaFuncSetAttribute(edge_kernel_mma, cudaFuncAttributeMaxDynamicSharedMemorySize, SM_EDGE);
    cudaFuncSetAttribute(proj_tf32,   cudaFuncAttributeMaxDynamicSharedMemorySize, SM_PROJ);
    cudaFuncSetAttribute(dual_tf32,   cudaFuncAttributeMaxDynamicSharedMemorySize, SM_DUAL);
    cudaFuncSetAttribute(update_tf32, cudaFuncAttributeMaxDynamicSharedMemorySize, SM_UPD);

    const int nChunks = (E + 31) / 32;
    int gEdge = 148 * 2;
    if (gEdge * 8 > nChunks) gEdge = (nChunks + 7) / 8;
    if (gEdge < 1) gEdge = 1;

    // ---- sort edges by dst (once; reused by all 4 layers) ----
    detect_idx_kernel<<<1, 32>>>((const unsigned int*)ei);
    cudaMemsetAsync(cnt, 0, NSCAN * sizeof(int));
    hist_kernel<<<1024, 256>>>(ei, E);
    scan1_kernel<<<NSCAN / 1024, 1024>>>();
    scan2_kernel<<<1, 32>>>(NSCAN / 1024);
    scan3_kernel<<<NSCAN / 1024, 1024>>>();
    scatter_kernel<<<1024, 256>>>(ei, eattr, E);

    // input projection
    proj_tf32<<<gN, 256, SM_PROJ>>>(x, lin_w, lin_b, h, M);

    for (int l = 0; l < 4; l++) {
        const float* W1 = msg_w1 + (size_t)l * 134 * 64;
        dual_tf32<<<gN, 256, SM_DUAL>>>(h, W1, msg_b1 + l * 64, Pab, M);
        edge_kernel_mma<<<gEdge, 256, SM_EDGE>>>(Pab,
                                                 W1 + 128 * 64,
                                                 msg_w2 + (size_t)l * 64 * 64,
                                                 msg_b2 + l * 64, agg, E);
        update_tf32<<<gN, 256, SM_UPD>>>(h, upd_w1 + (size_t)l * 128 * 64,
                                         upd_b1 + l * 64,
                                         upd_w2 + (size_t)l * 64 * 64,
                                         upd_b2 + l * 64, agg, h, M);
    }

    cudaMemsetAsync(d_out, 0, sizeof(float));
    pred_kernel<<<256, 256>>>(h, pred_w, pred_b, (float*)d_out, M);
}